// round 1
// baseline (speedup 1.0000x reference)
#include <cuda_runtime.h>
#include <cuda_bf16.h>

#define B_      1024
#define L_      50
#define K_      20
#define D_      64
#define NITEMS  100000
#define NUSERS  10000
#define ALPHA   0.2f

// scratch for pu (B x D) — device global (no allocation allowed)
__device__ float g_pu[B_ * D_];

// ---------------------------------------------------------------------------
// Kernel 1: recurrence + final attention + pu.  One warp per batch row.
// Lane l owns dims {l, l+32}. Memory (20x64) lives in registers.
// Only seq_length[b] steps are executed (stacked[T] == state after T steps).
// ---------------------------------------------------------------------------
__global__ void recur_kernel(const float* __restrict__ item,
                             const float* __restrict__ user,
                             const float* __restrict__ mem_init,
                             const int*   __restrict__ user_id,
                             const int*   __restrict__ seq,
                             const int*   __restrict__ seq_len)
{
    int warp = (blockIdx.x * blockDim.x + threadIdx.x) >> 5;
    int lane = threadIdx.x & 31;
    if (warp >= B_) return;
    const int b = warp;

    float m0[K_], m1[K_];
    const float* mi = mem_init + (size_t)b * K_ * D_;
#pragma unroll
    for (int k = 0; k < K_; k++) {
        m0[k] = mi[k * D_ + lane];
        m1[k] = mi[k * D_ + lane + 32];
    }

    const int T = seq_len[b];
    const int* sq = seq + b * L_;

    for (int t = 0; t < T; t++) {
        int idx = sq[t];
        float e0 = item[(size_t)idx * D_ + lane];
        float e1 = item[(size_t)idx * D_ + lane + 32];

        float s[K_];
#pragma unroll
        for (int k = 0; k < K_; k++) {
            float p = fmaf(m0[k], e0, m1[k] * e1);
#pragma unroll
            for (int off = 16; off > 0; off >>= 1)
                p += __shfl_xor_sync(0xffffffffu, p, off);
            s[k] = p;
        }
        float mx = s[0];
#pragma unroll
        for (int k = 1; k < K_; k++) mx = fmaxf(mx, s[k]);
        float sum = 0.f;
#pragma unroll
        for (int k = 0; k < K_; k++) { s[k] = expf(s[k] - mx); sum += s[k]; }
        float inv = 1.f / sum;

        float er0 = 1.f / (1.f + expf(-e0));
        float er1 = 1.f / (1.f + expf(-e1));
        float ad0 = tanhf(e0);
        float ad1 = tanhf(e1);
#pragma unroll
        for (int k = 0; k < K_; k++) {
            float z = s[k] * inv;
            m0[k] = m0[k] * (1.f - z * er0) + z * ad0;
            m1[k] = m1[k] * (1.f - z * er1) + z * ad1;
        }
    }

    // final attention with last item of the sequence (always column L-1)
    int lidx = sq[L_ - 1];
    float l0 = item[(size_t)lidx * D_ + lane];
    float l1 = item[(size_t)lidx * D_ + lane + 32];

    float s[K_];
#pragma unroll
    for (int k = 0; k < K_; k++) {
        float p = fmaf(m0[k], l0, m1[k] * l1);
#pragma unroll
        for (int off = 16; off > 0; off >>= 1)
            p += __shfl_xor_sync(0xffffffffu, p, off);
        s[k] = p;
    }
    float mx = s[0];
#pragma unroll
    for (int k = 1; k < K_; k++) mx = fmaxf(mx, s[k]);
    float sum = 0.f;
#pragma unroll
    for (int k = 0; k < K_; k++) { s[k] = expf(s[k] - mx); sum += s[k]; }
    float inv = 1.f / sum;

    float p0 = 0.f, p1 = 0.f;
#pragma unroll
    for (int k = 0; k < K_; k++) {
        float z = s[k] * inv;
        p0 = fmaf(z, m0[k], p0);
        p1 = fmaf(z, m1[k], p1);
    }

    int uid = user_id[b];
    g_pu[b * D_ + lane]      = user[(size_t)uid * D_ + lane]      + ALPHA * p0;
    g_pu[b * D_ + lane + 32] = user[(size_t)uid * D_ + lane + 32] + ALPHA * p1;
}

// ---------------------------------------------------------------------------
// Kernel 2: scores = pu (1024x64) @ item_table^T (64x100000), fp32.
// CTA tile 64(M) x 128(N), full K=64 resident in smem (exactly 48KB).
// 256 threads, 8x4 register micro-tile, float4 smem reads, float4 stores.
// ---------------------------------------------------------------------------
__global__ void __launch_bounds__(256) gemm_kernel(const float* __restrict__ Bt,   // item_table [N,K]
                                                   float* __restrict__ C)           // [B_, NITEMS]
{
    __shared__ __align__(16) float As[64][64];   // [k][m]
    __shared__ __align__(16) float Bs[64][128];  // [k][n]

    const int bm = blockIdx.y * 64;
    const int bn = blockIdx.x * 128;
    const int tid = threadIdx.x;

    // Load A tile (from g_pu): 64 rows x 64 k.  4 threads per row.
    {
        int m  = tid >> 2;
        int k0 = (tid & 3) * 16;
        const float4* src = (const float4*)(g_pu + (bm + m) * 64 + k0);
#pragma unroll
        for (int i = 0; i < 4; i++) {
            float4 v = src[i];
            As[k0 + i * 4 + 0][m] = v.x;
            As[k0 + i * 4 + 1][m] = v.y;
            As[k0 + i * 4 + 2][m] = v.z;
            As[k0 + i * 4 + 3][m] = v.w;
        }
    }
    // Load B tile: 128 rows (n) x 64 k.  2 threads per row.
    {
        int n  = tid >> 1;
        int k0 = (tid & 1) * 32;
        int gn = bn + n;
        if (gn < NITEMS) {
            const float4* src = (const float4*)(Bt + (size_t)gn * 64 + k0);
#pragma unroll
            for (int i = 0; i < 8; i++) {
                float4 v = src[i];
                Bs[k0 + i * 4 + 0][n] = v.x;
                Bs[k0 + i * 4 + 1][n] = v.y;
                Bs[k0 + i * 4 + 2][n] = v.z;
                Bs[k0 + i * 4 + 3][n] = v.w;
            }
        } else {
#pragma unroll
            for (int i = 0; i < 32; i++)
                Bs[k0 + i][n] = 0.f;
        }
    }
    __syncthreads();

    const int tx = tid & 31;   // n-direction, owns columns bn + tx*4 .. +3
    const int ty = tid >> 5;   // m-direction, owns rows bm + ty*8 .. +7

    float acc[8][4];
#pragma unroll
    for (int i = 0; i < 8; i++)
#pragma unroll
        for (int j = 0; j < 4; j++) acc[i][j] = 0.f;

#pragma unroll 16
    for (int k = 0; k < 64; k++) {
        float4 a0 = *(const float4*)&As[k][ty * 8];
        float4 a1 = *(const float4*)&As[k][ty * 8 + 4];
        float4 bv = *(const float4*)&Bs[k][tx * 4];
        float a[8] = {a0.x, a0.y, a0.z, a0.w, a1.x, a1.y, a1.z, a1.w};
        float bb[4] = {bv.x, bv.y, bv.z, bv.w};
#pragma unroll
        for (int i = 0; i < 8; i++)
#pragma unroll
            for (int j = 0; j < 4; j++)
                acc[i][j] = fmaf(a[i], bb[j], acc[i][j]);
    }

    int gn0 = bn + tx * 4;
    if (gn0 < NITEMS) {   // NITEMS % 4 == 0 so whole float4 is in-bounds
#pragma unroll
        for (int mi = 0; mi < 8; mi++) {
            int row = bm + ty * 8 + mi;
            float4 v = make_float4(acc[mi][0], acc[mi][1], acc[mi][2], acc[mi][3]);
            *(float4*)&C[(size_t)row * NITEMS + gn0] = v;
        }
    }
}

// ---------------------------------------------------------------------------
extern "C" void kernel_launch(void* const* d_in, const int* in_sizes, int n_in,
                              void* d_out, int out_size)
{
    const float* item_table  = (const float*)d_in[0];
    const float* user_table  = (const float*)d_in[1];
    const float* memory_init = (const float*)d_in[2];
    const int*   user_id     = (const int*)d_in[3];
    const int*   seq         = (const int*)d_in[4];
    const int*   seq_length  = (const int*)d_in[5];
    float*       scores      = (float*)d_out;

    // 1024 warps, 8 warps / block
    recur_kernel<<<B_ / 8, 256>>>(item_table, user_table, memory_init,
                                  user_id, seq, seq_length);

    dim3 grid((NITEMS + 127) / 128, B_ / 64);
    gemm_kernel<<<grid, 256>>>(item_table, scores);
}

// round 3
// speedup vs baseline: 1.2641x; 1.2641x over previous
#include <cuda_runtime.h>
#include <cuda_bf16.h>
#include <cstdint>

#define B_      1024
#define L_      50
#define K_      20
#define D_      64
#define NITEMS  100000
#define NUSERS  10000
#define ALPHA   0.2f

__device__ float g_pu[B_ * D_];

// ===========================================================================
// Kernel 1: recurrence + final attention + pu.  One warp per batch row.
// Lane l owns dims {l, l+32}; memory (20x64) in registers; only seq_length[b]
// steps executed.  Item embeddings prefetched 4 steps at a time.
// ===========================================================================
__global__ void recur_kernel(const float* __restrict__ item,
                             const float* __restrict__ user,
                             const float* __restrict__ mem_init,
                             const int*   __restrict__ user_id,
                             const int*   __restrict__ seq,
                             const int*   __restrict__ seq_len)
{
    int warp = (blockIdx.x * blockDim.x + threadIdx.x) >> 5;
    int lane = threadIdx.x & 31;
    if (warp >= B_) return;
    const int b = warp;

    float m0[K_], m1[K_];
    const float* mi = mem_init + (size_t)b * K_ * D_;
#pragma unroll
    for (int k = 0; k < K_; k++) {
        m0[k] = mi[k * D_ + lane];
        m1[k] = mi[k * D_ + lane + 32];
    }

    const int T = seq_len[b];
    const int* sq = seq + b * L_;

    for (int t0 = 0; t0 < T; t0 += 4) {
        int nt = min(4, T - t0);
        float e0[4], e1[4];
#pragma unroll
        for (int i = 0; i < 4; i++) {
            if (i < nt) {
                int idx = __ldg(sq + t0 + i);
                e0[i] = item[(size_t)idx * D_ + lane];
                e1[i] = item[(size_t)idx * D_ + lane + 32];
            }
        }
#pragma unroll
        for (int i = 0; i < 4; i++) {
            if (i >= nt) break;
            float s[K_];
#pragma unroll
            for (int k = 0; k < K_; k++) {
                float p = fmaf(m0[k], e0[i], m1[k] * e1[i]);
#pragma unroll
                for (int off = 16; off > 0; off >>= 1)
                    p += __shfl_xor_sync(0xffffffffu, p, off);
                s[k] = p;
            }
            float mx = s[0];
#pragma unroll
            for (int k = 1; k < K_; k++) mx = fmaxf(mx, s[k]);
            float sum = 0.f;
#pragma unroll
            for (int k = 0; k < K_; k++) { s[k] = expf(s[k] - mx); sum += s[k]; }
            float inv = 1.f / sum;
            float er0 = 1.f / (1.f + expf(-e0[i]));
            float er1 = 1.f / (1.f + expf(-e1[i]));
            float ad0 = tanhf(e0[i]);
            float ad1 = tanhf(e1[i]);
#pragma unroll
            for (int k = 0; k < K_; k++) {
                float z = s[k] * inv;
                m0[k] = m0[k] * (1.f - z * er0) + z * ad0;
                m1[k] = m1[k] * (1.f - z * er1) + z * ad1;
            }
        }
    }

    int lidx = __ldg(sq + L_ - 1);
    float l0 = item[(size_t)lidx * D_ + lane];
    float l1 = item[(size_t)lidx * D_ + lane + 32];

    float s[K_];
#pragma unroll
    for (int k = 0; k < K_; k++) {
        float p = fmaf(m0[k], l0, m1[k] * l1);
#pragma unroll
        for (int off = 16; off > 0; off >>= 1)
            p += __shfl_xor_sync(0xffffffffu, p, off);
        s[k] = p;
    }
    float mx = s[0];
#pragma unroll
    for (int k = 1; k < K_; k++) mx = fmaxf(mx, s[k]);
    float sum = 0.f;
#pragma unroll
    for (int k = 0; k < K_; k++) { s[k] = expf(s[k] - mx); sum += s[k]; }
    float inv = 1.f / sum;

    float p0 = 0.f, p1 = 0.f;
#pragma unroll
    for (int k = 0; k < K_; k++) {
        float z = s[k] * inv;
        p0 = fmaf(z, m0[k], p0);
        p1 = fmaf(z, m1[k], p1);
    }

    int uid = user_id[b];
    g_pu[b * D_ + lane]      = user[(size_t)uid * D_ + lane]      + ALPHA * p0;
    g_pu[b * D_ + lane + 32] = user[(size_t)uid * D_ + lane + 32] + ALPHA * p1;
}

// ===========================================================================
// Kernel 2: tf32 mma.sync GEMM.  C[1024,100000] = pu[1024,64] @ item[N,64]^T
// CTA tile 128(M) x 128(N), K=64 as 8 steps of m16n8k8.
// 8 warps: 2(M) x 4(N), warp tile 64x32 (4 m-tiles x 4 n-tiles).
// Tiles are converted to tf32 AND scattered into exact fragment layout in
// smem at load time, so the mainloop is pure LDS.128/LDS.64 + HMMA.
//   A frag smem: uint4 [ (ks*8 + mt)*32 + lane ]   (32 KB)
//   B frag smem: uint2 [ (ks*16 + nt)*32 + lane ]  (32 KB)
// Fragment maps (PTX m16n8k8.row.col):
//   A(m16 x k8): a0=(g, t) a1=(g+8, t) a2=(g, t+4) a3=(g+8, t+4), g=lane>>2, t=lane&3
//   B(k8 x n8):  b0=(t, g) b1=(t+4, g)
//   C(m16 x n8): c0=(g, 2t) c1=(g, 2t+1) c2=(g+8, 2t) c3=(g+8, 2t+1)
// ===========================================================================

#define GEMM_SMEM_BYTES (65536)

__device__ __forceinline__ uint32_t f2tf32(float x) {
    uint32_t u;
    asm("cvt.rn.tf32.f32 %0, %1;" : "=r"(u) : "f"(x));
    return u;
}

__device__ __forceinline__ void mma_tf32(float& c0, float& c1, float& c2, float& c3,
                                         uint32_t a0, uint32_t a1, uint32_t a2, uint32_t a3,
                                         uint32_t b0, uint32_t b1) {
    asm volatile("mma.sync.aligned.m16n8k8.row.col.f32.tf32.tf32.f32 "
                 "{%0,%1,%2,%3}, {%4,%5,%6,%7}, {%8,%9}, {%0,%1,%2,%3};"
                 : "+f"(c0), "+f"(c1), "+f"(c2), "+f"(c3)
                 : "r"(a0), "r"(a1), "r"(a2), "r"(a3), "r"(b0), "r"(b1));
}

// scatter one A element (local m, k) into fragment layout (index in u32 words)
__device__ __forceinline__ int a_frag_idx(int m, int k) {
    return ((((k >> 3) * 8 + (m >> 4)) * 32 + (m & 7) * 4 + (k & 3)) << 2)
         + ((m >> 3) & 1) + (((k >> 2) & 1) << 1);
}
// scatter one B element (local n, k)
__device__ __forceinline__ int b_frag_idx(int n, int k) {
    return ((((k >> 3) * 16 + (n >> 3)) * 32 + (n & 7) * 4 + (k & 3)) << 1)
         + ((k >> 2) & 1);
}

__global__ void __launch_bounds__(256, 2)
gemm_mma_kernel(const float* __restrict__ Bt,   // item_table [NITEMS, 64]
                float* __restrict__ C)           // [B_, NITEMS]
{
    extern __shared__ uint32_t fsm[];
    uint32_t* const Af = fsm;            // 8192 u32 = 32KB
    uint32_t* const Bf = fsm + 8192;     // 8192 u32 = 32KB

    const int tid  = threadIdx.x;
    const int wid  = tid >> 5;
    const int lane = tid & 31;

    const int bm = blockIdx.y * 128;
    const int bn = blockIdx.x * 128;

    // ---- load + convert + scatter tiles into fragment layout ----
    {
        const int row  = tid >> 1;          // 0..127
        const int half = tid & 1;           // k-half (32 k each)
        // A from g_pu
        const float4* asrc = (const float4*)(g_pu + (size_t)(bm + row) * 64) + half * 8;
#pragma unroll
        for (int i = 0; i < 8; i++) {
            float4 v = asrc[i];
            int k0 = half * 32 + i * 4;
            Af[a_frag_idx(row, k0 + 0)] = f2tf32(v.x);
            Af[a_frag_idx(row, k0 + 1)] = f2tf32(v.y);
            Af[a_frag_idx(row, k0 + 2)] = f2tf32(v.z);
            Af[a_frag_idx(row, k0 + 3)] = f2tf32(v.w);
        }
        // B from item_table (guard tail rows)
        const int gn = bn + row;
        if (gn < NITEMS) {
            const float4* bsrc = (const float4*)(Bt + (size_t)gn * 64) + half * 8;
#pragma unroll
            for (int i = 0; i < 8; i++) {
                float4 v = bsrc[i];
                int k0 = half * 32 + i * 4;
                Bf[b_frag_idx(row, k0 + 0)] = f2tf32(v.x);
                Bf[b_frag_idx(row, k0 + 1)] = f2tf32(v.y);
                Bf[b_frag_idx(row, k0 + 2)] = f2tf32(v.z);
                Bf[b_frag_idx(row, k0 + 3)] = f2tf32(v.w);
            }
        } else {
#pragma unroll
            for (int i = 0; i < 8; i++) {
                int k0 = half * 32 + i * 4;
                Bf[b_frag_idx(row, k0 + 0)] = 0u;
                Bf[b_frag_idx(row, k0 + 1)] = 0u;
                Bf[b_frag_idx(row, k0 + 2)] = 0u;
                Bf[b_frag_idx(row, k0 + 3)] = 0u;
            }
        }
    }
    __syncthreads();

    // ---- mainloop ----
    const int wm = (wid >> 2) & 1;   // M half of CTA (64 rows)
    const int wn = wid & 3;          // N quarter (32 cols)

    float acc[4][4][4];
#pragma unroll
    for (int i = 0; i < 4; i++)
#pragma unroll
        for (int j = 0; j < 4; j++)
#pragma unroll
            for (int q = 0; q < 4; q++) acc[i][j][q] = 0.f;

    const uint4* Af4 = (const uint4*)Af;
    const uint2* Bf2 = (const uint2*)Bf;

#pragma unroll
    for (int ks = 0; ks < 8; ks++) {
        uint4 a[4];
        uint2 b[4];
#pragma unroll
        for (int i = 0; i < 4; i++)
            a[i] = Af4[(ks * 8 + wm * 4 + i) * 32 + lane];
#pragma unroll
        for (int j = 0; j < 4; j++)
            b[j] = Bf2[(ks * 16 + wn * 4 + j) * 32 + lane];
#pragma unroll
        for (int i = 0; i < 4; i++)
#pragma unroll
            for (int j = 0; j < 4; j++)
                mma_tf32(acc[i][j][0], acc[i][j][1], acc[i][j][2], acc[i][j][3],
                         a[i].x, a[i].y, a[i].z, a[i].w, b[j].x, b[j].y);
    }

    // ---- epilogue: direct float2 stores (c0,c1 / c2,c3 are adjacent cols) ----
    const int g = lane >> 2;
    const int t = lane & 3;
#pragma unroll
    for (int i = 0; i < 4; i++) {
        int row0 = bm + wm * 64 + i * 16 + g;
#pragma unroll
        for (int j = 0; j < 4; j++) {
            int colbase = bn + wn * 32 + j * 8;
            if (colbase < NITEMS) {          // NITEMS % 8 == 0: whole n8-tile valid
                int col = colbase + 2 * t;
                *(float2*)(C + (size_t)row0 * NITEMS + col)
                    = make_float2(acc[i][j][0], acc[i][j][1]);
                *(float2*)(C + (size_t)(row0 + 8) * NITEMS + col)
                    = make_float2(acc[i][j][2], acc[i][j][3]);
            }
        }
    }
}

// ===========================================================================
extern "C" void kernel_launch(void* const* d_in, const int* in_sizes, int n_in,
                              void* d_out, int out_size)
{
    const float* item_table  = (const float*)d_in[0];
    const float* user_table  = (const float*)d_in[1];
    const float* memory_init = (const float*)d_in[2];
    const int*   user_id     = (const int*)d_in[3];
    const int*   seq         = (const int*)d_in[4];
    const int*   seq_length  = (const int*)d_in[5];
    float*       scores      = (float*)d_out;

    cudaFuncSetAttribute(gemm_mma_kernel,
                         cudaFuncAttributeMaxDynamicSharedMemorySize,
                         GEMM_SMEM_BYTES);

    recur_kernel<<<B_ / 8, 256>>>(item_table, user_table, memory_init,
                                  user_id, seq, seq_length);

    dim3 grid((NITEMS + 127) / 128, B_ / 128);
    gemm_mma_kernel<<<grid, 256, GEMM_SMEM_BYTES>>>(item_table, scores);
}

// round 4
// speedup vs baseline: 1.7022x; 1.3466x over previous
#include <cuda_runtime.h>
#include <cuda_bf16.h>
#include <cstdint>

#define B_      1024
#define L_      50
#define K_      20
#define D_      64
#define NITEMS  100000
#define NUSERS  10000
#define ALPHA   0.2f

#define MT_     (B_ / 16)          // 64 m16-tiles
#define NT_     (NITEMS / 8)       // 12500 n8-tiles
#define NT_PAD  12512              // padded to multiple of 16 (CTA covers 16 n8-tiles)

__device__ float g_pu[B_ * D_];
// fragment-ordered tf32 operands: [tile][ks(8)][lane(32)]
__device__ uint4 g_afrag[MT_ * 8 * 32];      // 256 KB
__device__ uint2 g_bfrag[NT_PAD * 8 * 32];   // 25.6 MB

__device__ __forceinline__ uint32_t f2tf32(float x) {
    uint32_t u;
    asm("cvt.rn.tf32.f32 %0, %1;" : "=r"(u) : "f"(x));
    return u;
}

__device__ __forceinline__ void mma_tf32(float& c0, float& c1, float& c2, float& c3,
                                         uint32_t a0, uint32_t a1, uint32_t a2, uint32_t a3,
                                         uint32_t b0, uint32_t b1) {
    asm volatile("mma.sync.aligned.m16n8k8.row.col.f32.tf32.tf32.f32 "
                 "{%0,%1,%2,%3}, {%4,%5,%6,%7}, {%8,%9}, {%0,%1,%2,%3};"
                 : "+f"(c0), "+f"(c1), "+f"(c2), "+f"(c3)
                 : "r"(a0), "r"(a1), "r"(a2), "r"(a3), "r"(b0), "r"(b1));
}

// ===========================================================================
// Kernel 1: recurrence + final attention + pu.  One warp per batch row.
// ===========================================================================
__global__ void recur_kernel(const float* __restrict__ item,
                             const float* __restrict__ user,
                             const float* __restrict__ mem_init,
                             const int*   __restrict__ user_id,
                             const int*   __restrict__ seq,
                             const int*   __restrict__ seq_len)
{
    int warp = (blockIdx.x * blockDim.x + threadIdx.x) >> 5;
    int lane = threadIdx.x & 31;
    if (warp >= B_) return;
    const int b = warp;

    float m0[K_], m1[K_];
    const float* mi = mem_init + (size_t)b * K_ * D_;
#pragma unroll
    for (int k = 0; k < K_; k++) {
        m0[k] = mi[k * D_ + lane];
        m1[k] = mi[k * D_ + lane + 32];
    }

    const int T = seq_len[b];
    const int* sq = seq + b * L_;

    for (int t0 = 0; t0 < T; t0 += 4) {
        int nt = min(4, T - t0);
        float e0[4], e1[4];
#pragma unroll
        for (int i = 0; i < 4; i++) {
            if (i < nt) {
                int idx = __ldg(sq + t0 + i);
                e0[i] = item[(size_t)idx * D_ + lane];
                e1[i] = item[(size_t)idx * D_ + lane + 32];
            }
        }
#pragma unroll
        for (int i = 0; i < 4; i++) {
            if (i >= nt) break;
            float s[K_];
#pragma unroll
            for (int k = 0; k < K_; k++) {
                float p = fmaf(m0[k], e0[i], m1[k] * e1[i]);
#pragma unroll
                for (int off = 16; off > 0; off >>= 1)
                    p += __shfl_xor_sync(0xffffffffu, p, off);
                s[k] = p;
            }
            float mx = s[0];
#pragma unroll
            for (int k = 1; k < K_; k++) mx = fmaxf(mx, s[k]);
            float sum = 0.f;
#pragma unroll
            for (int k = 0; k < K_; k++) { s[k] = expf(s[k] - mx); sum += s[k]; }
            float inv = 1.f / sum;
            float er0 = 1.f / (1.f + expf(-e0[i]));
            float er1 = 1.f / (1.f + expf(-e1[i]));
            float ad0 = tanhf(e0[i]);
            float ad1 = tanhf(e1[i]);
#pragma unroll
            for (int k = 0; k < K_; k++) {
                float z = s[k] * inv;
                m0[k] = m0[k] * (1.f - z * er0) + z * ad0;
                m1[k] = m1[k] * (1.f - z * er1) + z * ad1;
            }
        }
    }

    int lidx = __ldg(sq + L_ - 1);
    float l0 = item[(size_t)lidx * D_ + lane];
    float l1 = item[(size_t)lidx * D_ + lane + 32];

    float s[K_];
#pragma unroll
    for (int k = 0; k < K_; k++) {
        float p = fmaf(m0[k], l0, m1[k] * l1);
#pragma unroll
        for (int off = 16; off > 0; off >>= 1)
            p += __shfl_xor_sync(0xffffffffu, p, off);
        s[k] = p;
    }
    float mx = s[0];
#pragma unroll
    for (int k = 1; k < K_; k++) mx = fmaxf(mx, s[k]);
    float sum = 0.f;
#pragma unroll
    for (int k = 0; k < K_; k++) { s[k] = expf(s[k] - mx); sum += s[k]; }
    float inv = 1.f / sum;

    float p0 = 0.f, p1 = 0.f;
#pragma unroll
    for (int k = 0; k < K_; k++) {
        float z = s[k] * inv;
        p0 = fmaf(z, m0[k], p0);
        p1 = fmaf(z, m1[k], p1);
    }

    int uid = user_id[b];
    g_pu[b * D_ + lane]      = user[(size_t)uid * D_ + lane]      + ALPHA * p0;
    g_pu[b * D_ + lane + 32] = user[(size_t)uid * D_ + lane + 32] + ALPHA * p1;
}

// ===========================================================================
// Transform kernels: build fragment-ordered tf32 operands in global memory.
// m16n8k8.row.col fragment maps (validated in R3):
//   A: a0=(g,t) a1=(g+8,t) a2=(g,t+4) a3=(g+8,t+4),  g=lane>>2, t=lane&3
//   B: b0=(t,g) b1=(t+4,g)
// ===========================================================================
__global__ void afrag_kernel()
{
    int idx  = blockIdx.x * 256 + threadIdx.x;   // MT_*8*32 = 16384
    int lane = idx & 31;
    int ks   = (idx >> 5) & 7;
    int mt   = idx >> 8;
    int m0 = mt * 16 + (lane >> 2);
    int k0 = ks * 8  + (lane & 3);
    uint4 v;
    v.x = f2tf32(g_pu[m0 * 64 + k0]);
    v.y = f2tf32(g_pu[(m0 + 8) * 64 + k0]);
    v.z = f2tf32(g_pu[m0 * 64 + k0 + 4]);
    v.w = f2tf32(g_pu[(m0 + 8) * 64 + k0 + 4]);
    g_afrag[idx] = v;
}

__global__ void bfrag_kernel(const float* __restrict__ Bt)
{
    int idx  = blockIdx.x * 256 + threadIdx.x;   // NT_PAD*8*32
    int lane = idx & 31;
    int ks   = (idx >> 5) & 7;
    int nt   = idx >> 8;
    int n = nt * 8 + (lane >> 2);
    int k = ks * 8 + (lane & 3);
    uint2 v = make_uint2(0u, 0u);
    if (n < NITEMS) {
        v.x = f2tf32(__ldg(Bt + (size_t)n * 64 + k));
        v.y = f2tf32(__ldg(Bt + (size_t)n * 64 + k + 4));
    }
    g_bfrag[idx] = v;
}

// ===========================================================================
// Kernel 2: tf32 mma.sync GEMM, NO shared memory.
// CTA tile 128(M) x 128(N); 8 warps = 2(M) x 4(N); warp tile 64x32.
// Operands loaded directly from fragment-ordered global arrays (L2-resident)
// with coalesced LDG.128 / LDG.64.
// ===========================================================================
__global__ void __launch_bounds__(256, 2)
gemm_mma_kernel(float* __restrict__ C)           // [B_, NITEMS]
{
    const int tid  = threadIdx.x;
    const int wid  = tid >> 5;
    const int lane = tid & 31;

    const int wm = (wid >> 2) & 1;   // M half (64 rows)
    const int wn = wid & 3;          // N quarter (32 cols)

    const int mt0 = blockIdx.x * 8  + wm * 4;   // first m16-tile of this warp
    const int nt0 = blockIdx.y * 16 + wn * 4;   // first n8-tile of this warp

    const uint4* __restrict__ Ab = g_afrag + (size_t)mt0 * 256 + lane;
    const uint2* __restrict__ Bb = g_bfrag + (size_t)nt0 * 256 + lane;

    float acc[4][4][4];
#pragma unroll
    for (int i = 0; i < 4; i++)
#pragma unroll
        for (int j = 0; j < 4; j++)
#pragma unroll
            for (int q = 0; q < 4; q++) acc[i][j][q] = 0.f;

#pragma unroll
    for (int ks = 0; ks < 8; ks++) {
        uint4 a[4];
        uint2 b[4];
#pragma unroll
        for (int i = 0; i < 4; i++)
            a[i] = Ab[(size_t)(i * 8 + ks) * 32];
#pragma unroll
        for (int j = 0; j < 4; j++)
            b[j] = Bb[(size_t)(j * 8 + ks) * 32];
#pragma unroll
        for (int i = 0; i < 4; i++)
#pragma unroll
            for (int j = 0; j < 4; j++)
                mma_tf32(acc[i][j][0], acc[i][j][1], acc[i][j][2], acc[i][j][3],
                         a[i].x, a[i].y, a[i].z, a[i].w, b[j].x, b[j].y);
    }

    // epilogue: direct float2 stores (c0,c1 / c2,c3 are adjacent columns)
    const int g = lane >> 2;
    const int t = lane & 3;
    const int bm = blockIdx.x * 128 + wm * 64;
    const int bn = blockIdx.y * 128 + wn * 32;
#pragma unroll
    for (int i = 0; i < 4; i++) {
        int row0 = bm + i * 16 + g;
#pragma unroll
        for (int j = 0; j < 4; j++) {
            int colbase = bn + j * 8;
            if (colbase < NITEMS) {          // NITEMS % 8 == 0: whole n8-tile valid
                int col = colbase + 2 * t;
                *(float2*)(C + (size_t)row0 * NITEMS + col)
                    = make_float2(acc[i][j][0], acc[i][j][1]);
                *(float2*)(C + (size_t)(row0 + 8) * NITEMS + col)
                    = make_float2(acc[i][j][2], acc[i][j][3]);
            }
        }
    }
}

// ===========================================================================
extern "C" void kernel_launch(void* const* d_in, const int* in_sizes, int n_in,
                              void* d_out, int out_size)
{
    const float* item_table  = (const float*)d_in[0];
    const float* user_table  = (const float*)d_in[1];
    const float* memory_init = (const float*)d_in[2];
    const int*   user_id     = (const int*)d_in[3];
    const int*   seq         = (const int*)d_in[4];
    const int*   seq_length  = (const int*)d_in[5];
    float*       scores      = (float*)d_out;

    // B transform is independent of the recurrence — run it first.
    bfrag_kernel<<<NT_PAD, 256>>>(item_table);

    recur_kernel<<<B_ / 8, 256>>>(item_table, user_table, memory_init,
                                  user_id, seq, seq_length);

    afrag_kernel<<<MT_ * 8 * 32 / 256, 256>>>();

    dim3 grid(B_ / 128, NT_PAD / 16);    // (8, 782)
    gemm_mma_kernel<<<grid, 256>>>(scores);
}

// round 5
// speedup vs baseline: 1.7269x; 1.0145x over previous
#include <cuda_runtime.h>
#include <cuda_bf16.h>
#include <cstdint>

#define B_      1024
#define L_      50
#define K_      20
#define D_      64
#define NITEMS  100000
#define NUSERS  10000
#define ALPHA   0.2f

#define MT_     (B_ / 16)          // 64 m16-tiles
#define NT_PAD  12512              // n8-tiles padded (CTA covers 16)

// fragment-ordered tf32 operands
// A: [mt][ks(8)][lane(32)] uint4
__device__ uint4 g_afrag[MT_ * 8 * 32];        // 256 KB
// B: [nt][j(4)][lane(32)] uint4  (uint4 = b-frag pair for ks=2j and 2j+1)
__device__ uint4 g_bfrag[NT_PAD * 4 * 32];     // 25.6 MB

__device__ __forceinline__ uint32_t f2tf32(float x) {
    uint32_t u;
    asm("cvt.rn.tf32.f32 %0, %1;" : "=r"(u) : "f"(x));
    return u;
}

__device__ __forceinline__ void mma_tf32(float& c0, float& c1, float& c2, float& c3,
                                         uint32_t a0, uint32_t a1, uint32_t a2, uint32_t a3,
                                         uint32_t b0, uint32_t b1) {
    asm volatile("mma.sync.aligned.m16n8k8.row.col.f32.tf32.tf32.f32 "
                 "{%0,%1,%2,%3}, {%4,%5,%6,%7}, {%8,%9}, {%0,%1,%2,%3};"
                 : "+f"(c0), "+f"(c1), "+f"(c2), "+f"(c3)
                 : "r"(a0), "r"(a1), "r"(a2), "r"(a3), "r"(b0), "r"(b1));
}

// ===========================================================================
// Fused prep kernel (512 threads/block):
//   blocks [0, 64):   recurrence for 16 batch rows + A-fragment scatter
//   blocks [64, ...): B fragment transform (tf32 convert + reorder)
// ===========================================================================
#define RECUR_BLOCKS 64
#define BFRAG_BLOCKS (NT_PAD * 4 * 32 / 512)   // 3128
#define PU_STRIDE 68

__global__ void __launch_bounds__(512)
prep_kernel(const float* __restrict__ item,
            const float* __restrict__ user,
            const float* __restrict__ mem_init,
            const int*   __restrict__ user_id,
            const int*   __restrict__ seq,
            const int*   __restrict__ seq_len)
{
    __shared__ int   sseq[16 * L_];
    __shared__ float spu[16 * PU_STRIDE];

    const int tid = threadIdx.x;

    if (blockIdx.x >= RECUR_BLOCKS) {
        // ---------------- B fragment transform ----------------
        int fid  = (blockIdx.x - RECUR_BLOCKS) * 512 + tid;  // uint4 index
        int lane = fid & 31;
        int j    = (fid >> 5) & 3;
        int nt   = fid >> 7;
        int n = nt * 8 + (lane >> 2);
        int t = lane & 3;
        int k0 = j * 16 + t;
        uint4 v = make_uint4(0u, 0u, 0u, 0u);
        if (n < NITEMS) {
            const float* r = item + (size_t)n * 64;
            v.x = f2tf32(__ldg(r + k0));
            v.y = f2tf32(__ldg(r + k0 + 4));
            v.z = f2tf32(__ldg(r + k0 + 8));
            v.w = f2tf32(__ldg(r + k0 + 12));
        }
        g_bfrag[fid] = v;
        return;
    }

    // ---------------- recurrence: 16 warps = 16 batch rows ----------------
    const int wid  = tid >> 5;
    const int lane = tid & 31;
    const int b    = blockIdx.x * 16 + wid;

    // stage this block's 16 seq rows (contiguous 800 ints)
    for (int i = tid; i < 16 * L_; i += 512)
        sseq[i] = seq[blockIdx.x * 16 * L_ + i];
    __syncthreads();

    float m0[K_], m1[K_];
    const float* mi = mem_init + (size_t)b * K_ * D_;
#pragma unroll
    for (int k = 0; k < K_; k++) {
        m0[k] = mi[k * D_ + lane];
        m1[k] = mi[k * D_ + lane + 32];
    }

    const int T = seq_len[b];
    const int* sq = sseq + wid * L_;

    for (int t0 = 0; t0 < T; t0 += 8) {
        int nt = min(8, T - t0);
        float e0[8], e1[8];
#pragma unroll
        for (int i = 0; i < 8; i++) {
            if (i < nt) {
                int idx = sq[t0 + i];
                e0[i] = __ldg(item + (size_t)idx * D_ + lane);
                e1[i] = __ldg(item + (size_t)idx * D_ + lane + 32);
            }
        }
#pragma unroll
        for (int i = 0; i < 8; i++) {
            if (i >= nt) break;
            float s[K_];
#pragma unroll
            for (int k = 0; k < K_; k++) {
                float p = fmaf(m0[k], e0[i], m1[k] * e1[i]);
#pragma unroll
                for (int off = 16; off > 0; off >>= 1)
                    p += __shfl_xor_sync(0xffffffffu, p, off);
                s[k] = p;
            }
            float mx = s[0];
#pragma unroll
            for (int k = 1; k < K_; k++) mx = fmaxf(mx, s[k]);
            float sum = 0.f;
#pragma unroll
            for (int k = 0; k < K_; k++) { s[k] = expf(s[k] - mx); sum += s[k]; }
            float inv = 1.f / sum;
            float er0 = 1.f / (1.f + expf(-e0[i]));
            float er1 = 1.f / (1.f + expf(-e1[i]));
            float ad0 = tanhf(e0[i]);
            float ad1 = tanhf(e1[i]);
#pragma unroll
            for (int k = 0; k < K_; k++) {
                float z = s[k] * inv;
                m0[k] = m0[k] * (1.f - z * er0) + z * ad0;
                m1[k] = m1[k] * (1.f - z * er1) + z * ad1;
            }
        }
    }

    int lidx = sq[L_ - 1];
    float l0 = __ldg(item + (size_t)lidx * D_ + lane);
    float l1 = __ldg(item + (size_t)lidx * D_ + lane + 32);

    float s[K_];
#pragma unroll
    for (int k = 0; k < K_; k++) {
        float p = fmaf(m0[k], l0, m1[k] * l1);
#pragma unroll
        for (int off = 16; off > 0; off >>= 1)
            p += __shfl_xor_sync(0xffffffffu, p, off);
        s[k] = p;
    }
    float mx = s[0];
#pragma unroll
    for (int k = 1; k < K_; k++) mx = fmaxf(mx, s[k]);
    float sum = 0.f;
#pragma unroll
    for (int k = 0; k < K_; k++) { s[k] = expf(s[k] - mx); sum += s[k]; }
    float inv = 1.f / sum;

    float p0 = 0.f, p1 = 0.f;
#pragma unroll
    for (int k = 0; k < K_; k++) {
        float z = s[k] * inv;
        p0 = fmaf(z, m0[k], p0);
        p1 = fmaf(z, m1[k], p1);
    }

    int uid = user_id[b];
    spu[wid * PU_STRIDE + lane]      = user[(size_t)uid * D_ + lane]      + ALPHA * p0;
    spu[wid * PU_STRIDE + lane + 32] = user[(size_t)uid * D_ + lane + 32] + ALPHA * p1;
    __syncthreads();

    // ---- A fragment scatter for this block's m16-tile (mt = blockIdx.x) ----
    if (tid < 256) {
        int ks = tid >> 5;            // 0..7
        int ln = tid & 31;
        int g  = ln >> 2;
        int t  = ln & 3;
        int k0 = ks * 8 + t;
        uint4 v;
        v.x = f2tf32(spu[g * PU_STRIDE + k0]);
        v.y = f2tf32(spu[(g + 8) * PU_STRIDE + k0]);
        v.z = f2tf32(spu[g * PU_STRIDE + k0 + 4]);
        v.w = f2tf32(spu[(g + 8) * PU_STRIDE + k0 + 4]);
        g_afrag[(blockIdx.x * 8 + ks) * 32 + ln] = v;
    }
}

// ===========================================================================
// GEMM: C[1024,100000] = pu @ item^T, tf32 mma.sync, no smem.
// 512 threads = 16 warps: 2(M) x 8(N), warp tile 64x16 (4 m16 x 2 n8).
// CTA tile 128x128.  K pipelined as 4 stages of 2 k-steps, double-buffered
// register prefetch of fragment loads (all operands L2-resident).
// ===========================================================================
__global__ void __launch_bounds__(512, 1)
gemm_mma_kernel(float* __restrict__ C)
{
    const int tid  = threadIdx.x;
    const int wid  = tid >> 5;
    const int lane = tid & 31;

    const int wm = wid & 1;          // M half (64 rows)
    const int wn = wid >> 1;         // N slice (16 cols), 0..7

    const int mt0 = blockIdx.x * 8  + wm * 4;   // 4 m16-tiles
    const int nt0 = blockIdx.y * 16 + wn * 2;   // 2 n8-tiles

    const uint4* __restrict__ Ab = g_afrag + (size_t)mt0 * 256 + lane;
    const uint4* __restrict__ Bb = g_bfrag + (size_t)nt0 * 128 + lane;

    float acc[4][2][4];
#pragma unroll
    for (int i = 0; i < 4; i++)
#pragma unroll
        for (int j = 0; j < 2; j++)
#pragma unroll
            for (int q = 0; q < 4; q++) acc[i][j][q] = 0.f;

    uint4 a[2][2][4];   // [buf][s(ks within pair)][m-tile]
    uint4 b[2][2];      // [buf][n-tile]

    // prologue: stage 0
#pragma unroll
    for (int s = 0; s < 2; s++)
#pragma unroll
        for (int i = 0; i < 4; i++)
            a[0][s][i] = Ab[(size_t)(i * 8 + s) * 32];
#pragma unroll
    for (int jn = 0; jn < 2; jn++)
        b[0][jn] = Bb[(size_t)jn * 128];

#pragma unroll
    for (int j = 0; j < 4; j++) {
        const int cur = j & 1;
        const int nxt = cur ^ 1;
        if (j < 3) {
#pragma unroll
            for (int s = 0; s < 2; s++)
#pragma unroll
                for (int i = 0; i < 4; i++)
                    a[nxt][s][i] = Ab[(size_t)(i * 8 + 2 * (j + 1) + s) * 32];
#pragma unroll
            for (int jn = 0; jn < 2; jn++)
                b[nxt][jn] = Bb[(size_t)(jn * 4 + (j + 1)) * 32];
        }
#pragma unroll
        for (int s = 0; s < 2; s++)
#pragma unroll
            for (int i = 0; i < 4; i++)
#pragma unroll
                for (int jn = 0; jn < 2; jn++) {
                    uint32_t b0 = (s == 0) ? b[cur][jn].x : b[cur][jn].z;
                    uint32_t b1 = (s == 0) ? b[cur][jn].y : b[cur][jn].w;
                    mma_tf32(acc[i][jn][0], acc[i][jn][1], acc[i][jn][2], acc[i][jn][3],
                             a[cur][s][i].x, a[cur][s][i].y, a[cur][s][i].z, a[cur][s][i].w,
                             b0, b1);
                }
    }

    // epilogue
    const int g = lane >> 2;
    const int t = lane & 3;
    const int bm = blockIdx.x * 128 + wm * 64;
    const int bn = blockIdx.y * 128 + wn * 16;
#pragma unroll
    for (int i = 0; i < 4; i++) {
        int row0 = bm + i * 16 + g;
#pragma unroll
        for (int jn = 0; jn < 2; jn++) {
            int colbase = bn + jn * 8;
            if (colbase < NITEMS) {
                int col = colbase + 2 * t;
                *(float2*)(C + (size_t)row0 * NITEMS + col)
                    = make_float2(acc[i][jn][0], acc[i][jn][1]);
                *(float2*)(C + (size_t)(row0 + 8) * NITEMS + col)
                    = make_float2(acc[i][jn][2], acc[i][jn][3]);
            }
        }
    }
}

// ===========================================================================
extern "C" void kernel_launch(void* const* d_in, const int* in_sizes, int n_in,
                              void* d_out, int out_size)
{
    const float* item_table  = (const float*)d_in[0];
    const float* user_table  = (const float*)d_in[1];
    const float* memory_init = (const float*)d_in[2];
    const int*   user_id     = (const int*)d_in[3];
    const int*   seq         = (const int*)d_in[4];
    const int*   seq_length  = (const int*)d_in[5];
    float*       scores      = (float*)d_out;

    prep_kernel<<<RECUR_BLOCKS + BFRAG_BLOCKS, 512>>>(
        item_table, user_table, memory_init, user_id, seq, seq_length);

    dim3 grid(B_ / 128, NT_PAD / 16);    // (8, 782)
    gemm_mma_kernel<<<grid, 512>>>(scores);
}

// round 6
// speedup vs baseline: 2.1196x; 1.2274x over previous
#include <cuda_runtime.h>
#include <cuda_bf16.h>
#include <cstdint>

#define B_      1024
#define L_      50
#define K_      20
#define D_      64
#define NITEMS  100000
#define NUSERS  10000
#define ALPHA   0.2f

#define NT_PAD   12512              // n8-tiles padded to multiple of 16
#define NGROUPS  (NT_PAD / 16)      // 782 N-tile groups of 128 cols
#define STRIPS   8                  // M strips of 128 rows
#define SLOTS    18                 // CTAs per strip (8*18 = 144 CTAs, 1 wave)

__device__ float g_pu[B_ * D_];
// B fragments: [nt][j(4)][lane(32)] uint4 ; uint4 = b-frag pair for ks=2j,2j+1
__device__ uint4 g_bfrag[NT_PAD * 4 * 32];     // 25.6 MB

__device__ __forceinline__ uint32_t f2tf32(float x) {
    uint32_t u;
    asm("cvt.rn.tf32.f32 %0, %1;" : "=r"(u) : "f"(x));
    return u;
}
__device__ __forceinline__ uint32_t smem_u32(const void* p) {
    uint32_t a;
    asm("{ .reg .u64 t; cvta.to.shared.u64 t, %1; cvt.u32.u64 %0, t; }"
        : "=r"(a) : "l"(p));
    return a;
}
__device__ __forceinline__ void cp_async16(uint32_t dst, const void* src) {
    asm volatile("cp.async.cg.shared.global [%0], [%1], 16;"
                 :: "r"(dst), "l"(src) : "memory");
}
#define CP_COMMIT() asm volatile("cp.async.commit_group;" ::: "memory")
#define CP_WAIT(n)  asm volatile("cp.async.wait_group %0;" :: "n"(n) : "memory")

__device__ __forceinline__ void mma_tf32(float& c0, float& c1, float& c2, float& c3,
                                         uint32_t a0, uint32_t a1, uint32_t a2, uint32_t a3,
                                         uint32_t b0, uint32_t b1) {
    asm volatile("mma.sync.aligned.m16n8k8.row.col.f32.tf32.tf32.f32 "
                 "{%0,%1,%2,%3}, {%4,%5,%6,%7}, {%8,%9}, {%0,%1,%2,%3};"
                 : "+f"(c0), "+f"(c1), "+f"(c2), "+f"(c3)
                 : "r"(a0), "r"(a1), "r"(a2), "r"(a3), "r"(b0), "r"(b1));
}

// ===========================================================================
// Fused prep kernel (512 threads/block):
//   blocks [0, 64):   recurrence for 16 batch rows -> g_pu
//   blocks [64, ...): B fragment transform
// ===========================================================================
#define RECUR_BLOCKS 64
#define BFRAG_BLOCKS (NT_PAD * 4 * 32 / 512)   // 3128

__global__ void __launch_bounds__(512)
prep_kernel(const float* __restrict__ item,
            const float* __restrict__ user,
            const float* __restrict__ mem_init,
            const int*   __restrict__ user_id,
            const int*   __restrict__ seq,
            const int*   __restrict__ seq_len)
{
    __shared__ int sseq[16 * L_];
    const int tid = threadIdx.x;

    if (blockIdx.x >= RECUR_BLOCKS) {
        // ---------------- B fragment transform ----------------
        int fid  = (blockIdx.x - RECUR_BLOCKS) * 512 + tid;  // uint4 index
        int lane = fid & 31;
        int j    = (fid >> 5) & 3;
        int nt   = fid >> 7;
        int n = nt * 8 + (lane >> 2);
        int t = lane & 3;
        int k0 = j * 16 + t;
        uint4 v = make_uint4(0u, 0u, 0u, 0u);
        if (n < NITEMS) {
            const float* r = item + (size_t)n * 64;
            v.x = f2tf32(__ldg(r + k0));
            v.y = f2tf32(__ldg(r + k0 + 4));
            v.z = f2tf32(__ldg(r + k0 + 8));
            v.w = f2tf32(__ldg(r + k0 + 12));
        }
        g_bfrag[fid] = v;
        return;
    }

    // ---------------- recurrence: 16 warps = 16 batch rows ----------------
    const int wid  = tid >> 5;
    const int lane = tid & 31;
    const int b    = blockIdx.x * 16 + wid;

    for (int i = tid; i < 16 * L_; i += 512)
        sseq[i] = seq[blockIdx.x * 16 * L_ + i];
    __syncthreads();

    float m0[K_], m1[K_];
    const float* mi = mem_init + (size_t)b * K_ * D_;
#pragma unroll
    for (int k = 0; k < K_; k++) {
        m0[k] = mi[k * D_ + lane];
        m1[k] = mi[k * D_ + lane + 32];
    }

    const int T = seq_len[b];
    const int* sq = sseq + wid * L_;

    for (int t0 = 0; t0 < T; t0 += 8) {
        int nt = min(8, T - t0);
        float e0[8], e1[8];
#pragma unroll
        for (int i = 0; i < 8; i++) {
            if (i < nt) {
                int idx = sq[t0 + i];
                e0[i] = __ldg(item + (size_t)idx * D_ + lane);
                e1[i] = __ldg(item + (size_t)idx * D_ + lane + 32);
            }
        }
#pragma unroll
        for (int i = 0; i < 8; i++) {
            if (i >= nt) break;
            float s[K_];
#pragma unroll
            for (int k = 0; k < K_; k++) {
                float p = fmaf(m0[k], e0[i], m1[k] * e1[i]);
#pragma unroll
                for (int off = 16; off > 0; off >>= 1)
                    p += __shfl_xor_sync(0xffffffffu, p, off);
                s[k] = p;
            }
            float mx = s[0];
#pragma unroll
            for (int k = 1; k < K_; k++) mx = fmaxf(mx, s[k]);
            float sum = 0.f;
#pragma unroll
            for (int k = 0; k < K_; k++) { s[k] = __expf(s[k] - mx); sum += s[k]; }
            float inv = __fdividef(1.f, sum);
            float er0 = __fdividef(1.f, 1.f + __expf(-e0[i]));
            float er1 = __fdividef(1.f, 1.f + __expf(-e1[i]));
            float ex0 = __expf(2.f * e0[i]);
            float ex1 = __expf(2.f * e1[i]);
            float ad0 = __fdividef(ex0 - 1.f, ex0 + 1.f);
            float ad1 = __fdividef(ex1 - 1.f, ex1 + 1.f);
#pragma unroll
            for (int k = 0; k < K_; k++) {
                float z = s[k] * inv;
                m0[k] = m0[k] * (1.f - z * er0) + z * ad0;
                m1[k] = m1[k] * (1.f - z * er1) + z * ad1;
            }
        }
    }

    int lidx = sq[L_ - 1];
    float l0 = __ldg(item + (size_t)lidx * D_ + lane);
    float l1 = __ldg(item + (size_t)lidx * D_ + lane + 32);

    float s[K_];
#pragma unroll
    for (int k = 0; k < K_; k++) {
        float p = fmaf(m0[k], l0, m1[k] * l1);
#pragma unroll
        for (int off = 16; off > 0; off >>= 1)
            p += __shfl_xor_sync(0xffffffffu, p, off);
        s[k] = p;
    }
    float mx = s[0];
#pragma unroll
    for (int k = 1; k < K_; k++) mx = fmaxf(mx, s[k]);
    float sum = 0.f;
#pragma unroll
    for (int k = 0; k < K_; k++) { s[k] = __expf(s[k] - mx); sum += s[k]; }
    float inv = __fdividef(1.f, sum);

    float p0 = 0.f, p1 = 0.f;
#pragma unroll
    for (int k = 0; k < K_; k++) {
        float z = s[k] * inv;
        p0 = fmaf(z, m0[k], p0);
        p1 = fmaf(z, m1[k], p1);
    }

    int uid = user_id[b];
    g_pu[b * D_ + lane]      = user[(size_t)uid * D_ + lane]      + ALPHA * p0;
    g_pu[b * D_ + lane + 32] = user[(size_t)uid * D_ + lane + 32] + ALPHA * p1;
}

// ===========================================================================
// Persistent GEMM: C[1024,100000] = pu @ item^T (tf32 mma.sync)
// 144 CTAs (8 strips x 18 slots), 512 threads = 16 warps (4M x 4N),
// warp tile 32x32.  A (strip slice of pu) converted once into registers
// (uint4 a[2][8]).  B tiles (32KB/group) cp.async double-buffered in smem.
// ===========================================================================
#define GEMM_SMEM_BYTES (2 * 2048 * 16)   // 64 KB

__global__ void __launch_bounds__(512, 1)
gemm_persist(float* __restrict__ C)
{
    extern __shared__ uint4 sB[];          // [2][2048]
    const uint32_t sbase = smem_u32(sB);

    const int tid  = threadIdx.x;
    const int wid  = tid >> 5;
    const int lane = tid & 31;
    const int wm   = wid >> 2;             // 0..3 (M quarter, 32 rows)
    const int wn   = wid & 3;              // 0..3 (N quarter, 32 cols)
    const int g    = lane >> 2;
    const int t    = lane & 3;

    const int strip = blockIdx.x & 7;      // M strip of 128 rows
    const int slot  = blockIdx.x >> 3;     // 0..17

    // ---- A prologue: convert this warp's 32-row slice of pu into regs ----
    uint4 a[2][8];
    {
        const float* pu = g_pu + (size_t)(strip * 128 + wm * 32) * 64;
#pragma unroll
        for (int mi = 0; mi < 2; mi++) {
            int r0 = mi * 16 + g;
#pragma unroll
            for (int ks = 0; ks < 8; ks++) {
                int k0 = ks * 8 + t;
                a[mi][ks].x = f2tf32(pu[r0 * 64 + k0]);
                a[mi][ks].y = f2tf32(pu[(r0 + 8) * 64 + k0]);
                a[mi][ks].z = f2tf32(pu[r0 * 64 + k0 + 4]);
                a[mi][ks].w = f2tf32(pu[(r0 + 8) * 64 + k0 + 4]);
            }
        }
    }

    // ---- stage helper: copy group gidx (2048 uint4, contiguous) to buf ----
    // each thread copies 4 x 16B
    const int row_base = strip * 128 + wm * 32;

    // prologue stage
    if (slot < NGROUPS) {
        const uint4* src = g_bfrag + (size_t)slot * 2048 + tid;
        uint32_t dst = sbase + (uint32_t)tid * 16u;
#pragma unroll
        for (int r = 0; r < 4; r++)
            cp_async16(dst + r * 512 * 16, src + r * 512);
        CP_COMMIT();
    }

    int iter = 0;
    for (int grp = slot; grp < NGROUPS; grp += SLOTS, iter++) {
        const int buf = iter & 1;
        const int nxt = grp + SLOTS;
        if (nxt < NGROUPS) {
            const uint4* src = g_bfrag + (size_t)nxt * 2048 + tid;
            uint32_t dst = sbase + (uint32_t)((buf ^ 1) * 2048 + tid) * 16u;
#pragma unroll
            for (int r = 0; r < 4; r++)
                cp_async16(dst + r * 512 * 16, src + r * 512);
            CP_COMMIT();
            CP_WAIT(1);
        } else {
            CP_WAIT(0);
        }
        __syncthreads();

        float acc[2][4][4];
#pragma unroll
        for (int i = 0; i < 2; i++)
#pragma unroll
            for (int j = 0; j < 4; j++)
#pragma unroll
                for (int q = 0; q < 4; q++) acc[i][j][q] = 0.f;

        const uint4* Bs = sB + buf * 2048;
#pragma unroll
        for (int j = 0; j < 4; j++) {
            uint4 b[4];
#pragma unroll
            for (int ni = 0; ni < 4; ni++)
                b[ni] = Bs[((wn * 4 + ni) * 4 + j) * 32 + lane];
#pragma unroll
            for (int s = 0; s < 2; s++) {
                const int ks = 2 * j + s;
#pragma unroll
                for (int mi = 0; mi < 2; mi++)
#pragma unroll
                    for (int ni = 0; ni < 4; ni++) {
                        uint32_t b0 = (s == 0) ? b[ni].x : b[ni].z;
                        uint32_t b1 = (s == 0) ? b[ni].y : b[ni].w;
                        mma_tf32(acc[mi][ni][0], acc[mi][ni][1],
                                 acc[mi][ni][2], acc[mi][ni][3],
                                 a[mi][ks].x, a[mi][ks].y, a[mi][ks].z, a[mi][ks].w,
                                 b0, b1);
                    }
            }
        }

        // ---- epilogue: streaming stores ----
#pragma unroll
        for (int mi = 0; mi < 2; mi++) {
            int row0 = row_base + mi * 16 + g;
#pragma unroll
            for (int ni = 0; ni < 4; ni++) {
                int cb = grp * 128 + wn * 32 + ni * 8;
                if (cb < NITEMS) {           // NITEMS % 8 == 0
                    int col = cb + 2 * t;
                    __stcs((float2*)(C + (size_t)row0 * NITEMS + col),
                           make_float2(acc[mi][ni][0], acc[mi][ni][1]));
                    __stcs((float2*)(C + (size_t)(row0 + 8) * NITEMS + col),
                           make_float2(acc[mi][ni][2], acc[mi][ni][3]));
                }
            }
        }
        __syncthreads();
    }
}

// ===========================================================================
extern "C" void kernel_launch(void* const* d_in, const int* in_sizes, int n_in,
                              void* d_out, int out_size)
{
    const float* item_table  = (const float*)d_in[0];
    const float* user_table  = (const float*)d_in[1];
    const float* memory_init = (const float*)d_in[2];
    const int*   user_id     = (const int*)d_in[3];
    const int*   seq         = (const int*)d_in[4];
    const int*   seq_length  = (const int*)d_in[5];
    float*       scores      = (float*)d_out;

    cudaFuncSetAttribute(gemm_persist,
                         cudaFuncAttributeMaxDynamicSharedMemorySize,
                         GEMM_SMEM_BYTES);

    prep_kernel<<<RECUR_BLOCKS + BFRAG_BLOCKS, 512>>>(
        item_table, user_table, memory_init, user_id, seq, seq_length);

    gemm_persist<<<STRIPS * SLOTS, 512, GEMM_SMEM_BYTES>>>(scores);
}

// round 7
// speedup vs baseline: 2.7570x; 1.3007x over previous
#include <cuda_runtime.h>
#include <cuda_bf16.h>
#include <cstdint>

#define B_      1024
#define L_      50
#define K_      20
#define D_      64
#define NITEMS  100000
#define NUSERS  10000
#define ALPHA   0.2f

#define NT_PAD   12512              // n8-tiles padded to multiple of 16
#define NGROUPS  (NT_PAD / 16)      // 782 groups of 128 cols
#define STRIPS   8
#define SLOTS    18                 // 8*18 = 144 CTAs, one wave

__device__ float g_pu[B_ * D_];
// B fragments: [nt][j(4)][lane(32)] uint4 (pair of k-steps 2j,2j+1)
// column-paired permutation baked in (see bfrag_body)
__device__ uint4 g_bfrag[NT_PAD * 4 * 32];     // 25.6 MB

__device__ __forceinline__ uint32_t f2tf32(float x) {
    uint32_t u;
    asm("cvt.rn.tf32.f32 %0, %1;" : "=r"(u) : "f"(x));
    return u;
}
__device__ __forceinline__ uint32_t smem_u32(const void* p) {
    uint32_t a;
    asm("{ .reg .u64 t; cvta.to.shared.u64 t, %1; cvt.u32.u64 %0, t; }"
        : "=r"(a) : "l"(p));
    return a;
}
__device__ __forceinline__ void cp_async16(uint32_t dst, const void* src) {
    asm volatile("cp.async.cg.shared.global [%0], [%1], 16;"
                 :: "r"(dst), "l"(src) : "memory");
}
#define CP_COMMIT() asm volatile("cp.async.commit_group;" ::: "memory")
#define CP_WAIT(n)  asm volatile("cp.async.wait_group %0;" :: "n"(n) : "memory")

__device__ __forceinline__ void mma_tf32(float& c0, float& c1, float& c2, float& c3,
                                         uint32_t a0, uint32_t a1, uint32_t a2, uint32_t a3,
                                         uint32_t b0, uint32_t b1) {
    asm volatile("mma.sync.aligned.m16n8k8.row.col.f32.tf32.tf32.f32 "
                 "{%0,%1,%2,%3}, {%4,%5,%6,%7}, {%8,%9}, {%0,%1,%2,%3};"
                 : "+f"(c0), "+f"(c1), "+f"(c2), "+f"(c3)
                 : "r"(a0), "r"(a1), "r"(a2), "r"(a3), "r"(b0), "r"(b1));
}

// tree sum of 20 floats (depth 5)
__device__ __forceinline__ float tree_sum20(const float* s) {
    float t1[10];
#pragma unroll
    for (int i = 0; i < 10; i++) t1[i] = s[2 * i] + s[2 * i + 1];
    float t2[5];
#pragma unroll
    for (int i = 0; i < 5; i++) t2[i] = t1[2 * i] + t1[2 * i + 1];
    return ((t2[0] + t2[1]) + (t2[2] + t2[3])) + t2[4];
}

// ===========================================================================
// Fused prep kernel (256 threads/block):
//   blocks [0,128):  recurrence for 8 batch rows -> g_pu
//   blocks [128,..): B fragment transform (tf32 + column-pair permutation)
// ===========================================================================
#define RECUR_BLOCKS 128
#define BFRAG_BLOCKS (NT_PAD * 4 * 32 / 256)   // 6256

__global__ void __launch_bounds__(256)
prep_kernel(const float* __restrict__ item,
            const float* __restrict__ user,
            const float* __restrict__ mem_init,
            const int*   __restrict__ user_id,
            const int*   __restrict__ seq,
            const int*   __restrict__ seq_len)
{
    __shared__ int sseq[8 * L_];
    const int tid = threadIdx.x;

    if (blockIdx.x >= RECUR_BLOCKS) {
        // ---------------- B fragment transform ----------------
        int fid  = (blockIdx.x - RECUR_BLOCKS) * 256 + tid;  // uint4 index
        int lane = fid & 31;
        int j    = (fid >> 5) & 3;
        int nt   = fid >> 7;
        int w    = lane >> 2;            // b-frag column (= output col of n8 tile)
        int t    = lane & 3;
        int par  = nt & 1;
        // column-pair permutation within the 16-col group
        int n = (nt >> 1) * 16 + ((w & 1) ? (2 * w - 1 + 2 * par) : (2 * w + 2 * par));
        int k0 = j * 16 + t;
        uint4 v = make_uint4(0u, 0u, 0u, 0u);
        if (n < NITEMS) {
            const float* r = item + (size_t)n * 64;
            v.x = f2tf32(__ldg(r + k0));
            v.y = f2tf32(__ldg(r + k0 + 4));
            v.z = f2tf32(__ldg(r + k0 + 8));
            v.w = f2tf32(__ldg(r + k0 + 12));
        }
        g_bfrag[fid] = v;
        return;
    }

    // ---------------- recurrence: 8 warps = 8 batch rows ----------------
    const int wid  = tid >> 5;
    const int lane = tid & 31;
    const int b    = blockIdx.x * 8 + wid;

    for (int i = tid; i < 8 * L_; i += 256)
        sseq[i] = seq[blockIdx.x * 8 * L_ + i];
    __syncthreads();

    float m0[K_], m1[K_];
    const float* mi = mem_init + (size_t)b * K_ * D_;
#pragma unroll
    for (int k = 0; k < K_; k++) {
        m0[k] = mi[k * D_ + lane];
        m1[k] = mi[k * D_ + lane + 32];
    }

    const int T = seq_len[b];
    const int* sq = sseq + wid * L_;

    for (int t0 = 0; t0 < T; t0 += 8) {
        int nt = min(8, T - t0);
        float e0[8], e1[8];
#pragma unroll
        for (int i = 0; i < 8; i++) {
            if (i < nt) {
                int idx = sq[t0 + i];
                e0[i] = __ldg(item + (size_t)idx * D_ + lane);
                e1[i] = __ldg(item + (size_t)idx * D_ + lane + 32);
            }
        }
#pragma unroll
        for (int i = 0; i < 8; i++) {
            if (i >= nt) break;
            float s[K_];
#pragma unroll
            for (int k = 0; k < K_; k++) {
                float p = fmaf(m0[k], e0[i], m1[k] * e1[i]);
#pragma unroll
                for (int off = 16; off > 0; off >>= 1)
                    p += __shfl_xor_sync(0xffffffffu, p, off);
                s[k] = p;
            }
            // softmax without max-subtraction: |s| <= ~1.3, exp is safe
#pragma unroll
            for (int k = 0; k < K_; k++) s[k] = __expf(s[k]);
            float inv = __fdividef(1.f, tree_sum20(s));
            float er0 = __fdividef(1.f, 1.f + __expf(-e0[i]));
            float er1 = __fdividef(1.f, 1.f + __expf(-e1[i]));
            float ex0 = __expf(2.f * e0[i]);
            float ex1 = __expf(2.f * e1[i]);
            float ad0 = __fdividef(ex0 - 1.f, ex0 + 1.f);
            float ad1 = __fdividef(ex1 - 1.f, ex1 + 1.f);
#pragma unroll
            for (int k = 0; k < K_; k++) {
                float z = s[k] * inv;
                m0[k] = m0[k] * (1.f - z * er0) + z * ad0;
                m1[k] = m1[k] * (1.f - z * er1) + z * ad1;
            }
        }
    }

    int lidx = sq[L_ - 1];
    float l0 = __ldg(item + (size_t)lidx * D_ + lane);
    float l1 = __ldg(item + (size_t)lidx * D_ + lane + 32);

    float s[K_];
#pragma unroll
    for (int k = 0; k < K_; k++) {
        float p = fmaf(m0[k], l0, m1[k] * l1);
#pragma unroll
        for (int off = 16; off > 0; off >>= 1)
            p += __shfl_xor_sync(0xffffffffu, p, off);
        s[k] = __expf(p);
    }
    float inv = __fdividef(1.f, tree_sum20(s));

    float p0 = 0.f, p1 = 0.f;
#pragma unroll
    for (int k = 0; k < K_; k++) {
        float z = s[k] * inv;
        p0 = fmaf(z, m0[k], p0);
        p1 = fmaf(z, m1[k], p1);
    }

    int uid = user_id[b];
    g_pu[b * D_ + lane]      = user[(size_t)uid * D_ + lane]      + ALPHA * p0;
    g_pu[b * D_ + lane + 32] = user[(size_t)uid * D_ + lane + 32] + ALPHA * p1;
}

// ===========================================================================
// Persistent GEMM: 144 CTAs (8 strips x 18 slots), 512 thr = 16 warps (4Mx4N).
// Warp tile 32x32 (2 m16 x 2 col-paired 16-groups).  A in regs.
// 3-stage cp.async ring (96KB), ONE __syncthreads per iteration.
// Epilogue: STG.128 streaming stores (column pairing makes 4 cols contiguous).
// ===========================================================================
#define TILE_U4   2048                      // uint4 per 128-col group
#define GEMM_SMEM_BYTES (3 * TILE_U4 * 16)  // 96 KB

__global__ void __launch_bounds__(512, 1)
gemm_persist(float* __restrict__ C)
{
    extern __shared__ uint4 sB[];          // [3][2048]
    const uint32_t sbase = smem_u32(sB);

    const int tid  = threadIdx.x;
    const int wid  = tid >> 5;
    const int lane = tid & 31;
    const int wm   = wid >> 2;             // 0..3 (32 rows)
    const int wn   = wid & 3;              // 0..3 (32 cols)
    const int g    = lane >> 2;
    const int t    = lane & 3;

    const int strip = blockIdx.x & 7;
    const int slot  = blockIdx.x >> 3;

    // ---- A: convert this warp's 32-row slice of pu into registers ----
    uint4 a[2][8];
    {
        const float* pu = g_pu + (size_t)(strip * 128 + wm * 32) * 64;
#pragma unroll
        for (int mi = 0; mi < 2; mi++) {
            int r0 = mi * 16 + g;
#pragma unroll
            for (int ks = 0; ks < 8; ks++) {
                int k0 = ks * 8 + t;
                a[mi][ks].x = f2tf32(pu[r0 * 64 + k0]);
                a[mi][ks].y = f2tf32(pu[(r0 + 8) * 64 + k0]);
                a[mi][ks].z = f2tf32(pu[r0 * 64 + k0 + 4]);
                a[mi][ks].w = f2tf32(pu[(r0 + 8) * 64 + k0 + 4]);
            }
        }
    }

    const int row_base = strip * 128 + wm * 32;

    // ---- prologue: stage groups for iter 0,1 into buffers 0,1 ----
#pragma unroll
    for (int pf = 0; pf < 2; pf++) {
        int grp = slot + pf * SLOTS;
        if (grp < NGROUPS) {
            const uint4* src = g_bfrag + (size_t)grp * TILE_U4 + tid;
            uint32_t dst = sbase + (uint32_t)(pf * TILE_U4 + tid) * 16u;
#pragma unroll
            for (int r = 0; r < 4; r++)
                cp_async16(dst + r * 512 * 16, src + r * 512);
        }
        CP_COMMIT();
    }

    int iter = 0;
    for (int grp = slot; grp < NGROUPS; grp += SLOTS, iter++) {
        const int buf = iter - (iter / 3) * 3;          // iter % 3
        // wait for this iter's buffer, then barrier (also frees buf (iter-1)%3)
        CP_WAIT(1);
        __syncthreads();

        // prefetch iter+2 into buffer (iter+2)%3 == (iter-1)%3 (now free)
        {
            int nxt = grp + 2 * SLOTS;
            if (nxt < NGROUPS) {
                const int pbuf = (buf + 2 >= 3) ? buf - 1 : buf + 2;
                const uint4* src = g_bfrag + (size_t)nxt * TILE_U4 + tid;
                uint32_t dst = sbase + (uint32_t)(pbuf * TILE_U4 + tid) * 16u;
#pragma unroll
                for (int r = 0; r < 4; r++)
                    cp_async16(dst + r * 512 * 16, src + r * 512);
            }
            CP_COMMIT();
        }

        // ---- compute: acc[mi][pair][parity][4] ----
        float acc[2][2][2][4];
#pragma unroll
        for (int i = 0; i < 2; i++)
#pragma unroll
            for (int p = 0; p < 2; p++)
#pragma unroll
                for (int q = 0; q < 2; q++)
#pragma unroll
                    for (int r = 0; r < 4; r++) acc[i][p][q][r] = 0.f;

        const uint4* Bs = sB + buf * TILE_U4;
#pragma unroll
        for (int j = 0; j < 4; j++) {
            uint4 b[2][2];
#pragma unroll
            for (int p = 0; p < 2; p++)
#pragma unroll
                for (int q = 0; q < 2; q++)
                    b[p][q] = Bs[((wn * 4 + p * 2 + q) * 4 + j) * 32 + lane];
#pragma unroll
            for (int s = 0; s < 2; s++) {
                const int ks = 2 * j + s;
#pragma unroll
                for (int mi = 0; mi < 2; mi++)
#pragma unroll
                    for (int p = 0; p < 2; p++)
#pragma unroll
                        for (int q = 0; q < 2; q++) {
                            uint32_t b0 = (s == 0) ? b[p][q].x : b[p][q].z;
                            uint32_t b1 = (s == 0) ? b[p][q].y : b[p][q].w;
                            mma_tf32(acc[mi][p][q][0], acc[mi][p][q][1],
                                     acc[mi][p][q][2], acc[mi][p][q][3],
                                     a[mi][ks].x, a[mi][ks].y, a[mi][ks].z, a[mi][ks].w,
                                     b0, b1);
                        }
            }
        }

        // ---- epilogue: STG.128 streaming stores (no barrier after) ----
#pragma unroll
        for (int mi = 0; mi < 2; mi++) {
            int row0 = row_base + mi * 16 + g;
#pragma unroll
            for (int p = 0; p < 2; p++) {
                int base16 = grp * 128 + wn * 32 + p * 16;
                if (base16 < NITEMS) {       // NITEMS % 16 == 0
                    int col = base16 + 4 * t;
                    __stcs((float4*)(C + (size_t)row0 * NITEMS + col),
                           make_float4(acc[mi][p][0][0], acc[mi][p][0][1],
                                       acc[mi][p][1][0], acc[mi][p][1][1]));
                    __stcs((float4*)(C + (size_t)(row0 + 8) * NITEMS + col),
                           make_float4(acc[mi][p][0][2], acc[mi][p][0][3],
                                       acc[mi][p][1][2], acc[mi][p][1][3]));
                }
            }
        }
    }
}

// ===========================================================================
extern "C" void kernel_launch(void* const* d_in, const int* in_sizes, int n_in,
                              void* d_out, int out_size)
{
    const float* item_table  = (const float*)d_in[0];
    const float* user_table  = (const float*)d_in[1];
    const float* memory_init = (const float*)d_in[2];
    const int*   user_id     = (const int*)d_in[3];
    const int*   seq         = (const int*)d_in[4];
    const int*   seq_length  = (const int*)d_in[5];
    float*       scores      = (float*)d_out;

    cudaFuncSetAttribute(gemm_persist,
                         cudaFuncAttributeMaxDynamicSharedMemorySize,
                         GEMM_SMEM_BYTES);

    prep_kernel<<<RECUR_BLOCKS + BFRAG_BLOCKS, 256>>>(
        item_table, user_table, memory_init, user_id, seq, seq_length);

    gemm_persist<<<STRIPS * SLOTS, 512, GEMM_SMEM_BYTES>>>(scores);
}